// round 13
// baseline (speedup 1.0000x reference)
#include <cuda_runtime.h>
#include <cstdint>

// ---------------- configuration (fixed for this problem instance) ----------------
#define OUT_DIM   640            // rep_dim = out_dim for METADATA [64,64,32,32]
#define NG        (OUT_DIM/32)   // 20 output groups of 32
#define ROWS      32             // batch rows per main-kernel block (lane = row)
#define KCAP      24             // max terms per single output (measured <= 20)
#define MAX_M     8192           // cap on sparse term count (actual ~4.7K)
#define PAD       33             // smem row pitch (conflict-free transpose + gather)

// ---------------- device scratch (no runtime allocation allowed) ----------------
// meta[o*KCAP + k] = {cg_bits, i1*PAD*4, i2*PAD*4, 0} -- premultiplied byte offsets
__device__ uint4 d_meta[OUT_DIM * KCAP];
__device__ int   d_len[OUT_DIM];     // exact terms per output (<= KCAP)

// ---------------- preprocessing: one block per output group, 1024 threads ----------------
// Stage ro in smem; 32 warps two-pass scan (chunk ~ M/32): pass1 counts matches
// per (warp-slice, lane-output), smem exchange gives deterministic exclusive
// offsets (slot = rank of term in m-order), pass2 scatters packed meta.
__global__ __launch_bounds__(1024) void k_prep(const int* __restrict__ ro,
                                               const int* __restrict__ r1,
                                               const int* __restrict__ r2,
                                               const float* __restrict__ cg,
                                               int M) {
    __shared__ int s_ro[MAX_M];
    __shared__ int s_cnt[32][32];
    int og = blockIdx.x;

    for (int i = threadIdx.x; i < M; i += 1024) s_ro[i] = ro[i];
    __syncthreads();

    int w = threadIdx.x >> 5, lane = threadIdx.x & 31;
    int o = og * 32 + lane;
    int chunk = (M + 31) >> 5;
    int mlo = w * chunk;
    int mhi = mlo + chunk; if (mhi > M) mhi = M;

    int cnt = 0;
    for (int m = mlo; m < mhi; m++) cnt += (s_ro[m] == o);
    s_cnt[w][lane] = cnt;
    __syncthreads();

    int off = 0;
    for (int ww = 0; ww < w; ww++) off += s_cnt[ww][lane];

    int k = off;
    for (int m = mlo; m < mhi; m++) {
        if (s_ro[m] == o) {
            if (k < KCAP) {
                d_meta[o * KCAP + k] =
                    make_uint4(__float_as_uint(cg[m]),
                               (unsigned)r1[m] * (PAD * 4u),
                               (unsigned)r2[m] * (PAD * 4u), 0u);
            }
            k++;
        }
    }

    if (w == 0) {
        int tot = 0;
        #pragma unroll
        for (int ww = 0; ww < 32; ww++) tot += s_cnt[ww][lane];
        if (tot > KCAP) tot = KCAP;
        d_len[o] = tot;
    }
}

// ---------------- main kernel ----------------
// Block: 640 threads (20 warps), 32 batch rows. Warp w owns output group w;
// lane = batch row. x1/x2 staged TRANSPOSED in smem (pitch PAD=33 floats:
// conflict-free for both the transpose STS and the per-term gathers).
// Per term: one warp-uniform LDG.128 of meta (broadcast, premultiplied smem
// byte offsets), two conflict-free LDS.32 gathers serving all 32 rows, 2 FP.
// 32 accumulators/lane; epilogue transposes via the x1T region (after a block
// barrier) so global stores are fully coalesced. No atomics anywhere.
__global__ __launch_bounds__(640) void k_main(const float* __restrict__ x1,
                                              const float* __restrict__ x2,
                                              float* __restrict__ out, int N) {
    extern __shared__ float sm[];
    float* x1T = sm;                     // [640 cols][PAD rows]
    float* x2T = sm + OUT_DIM * PAD;

    int tid = threadIdx.x;
    int row0 = blockIdx.x * ROWS;
    int rows_here = N - row0; if (rows_here > ROWS) rows_here = ROWS;

    // load + transpose: thread i -> (r = i/640, c = i%640); consecutive tid =
    // consecutive c (coalesced LDG.32), STS banks (c+r)%32 (conflict-free).
    for (int i = tid; i < rows_here * OUT_DIM; i += 640) {
        int r = i / OUT_DIM;
        int c = i - r * OUT_DIM;
        size_t g = (size_t)(row0 + r) * OUT_DIM + c;
        x1T[c * PAD + r] = x1[g];
        x2T[c * PAD + r] = x2[g];
    }
    __syncthreads();

    int w = tid >> 5, lane = tid & 31;
    const char* b1 = (const char*)x1T + lane * 4;
    const char* b2 = (const char*)x2T + lane * 4;

    float acc[32];
    #pragma unroll
    for (int j = 0; j < 32; j++) {
        int o = w * 32 + j;
        int len = d_len[o];                      // warp-uniform
        const uint4* p = d_meta + o * KCAP;
        float a = 0.0f;
        #pragma unroll 4
        for (int k = 0; k < len; k++) {
            uint4 mv = p[k];                     // uniform broadcast LDG.128
            float c  = __uint_as_float(mv.x);
            float va = *(const float*)(b1 + mv.y);
            float vb = *(const float*)(b2 + mv.z);
            a = fmaf(c * va, vb, a);
        }
        acc[j] = a;
    }

    // epilogue: all gathers done -> reuse x1T as per-warp 32x33 transpose tiles
    __syncthreads();
    float* tile = x1T + w * (32 * PAD);          // 20*1056 = 21120 = 640*33 (exact fit)
    #pragma unroll
    for (int j = 0; j < 32; j++) tile[j * PAD + lane] = acc[j];
    __syncwarp();
    #pragma unroll
    for (int r = 0; r < 32; r++) {
        if (row0 + r < N)
            out[(size_t)(row0 + r) * OUT_DIM + w * 32 + lane] = tile[lane * PAD + r];
    }
}

// ---------------- launch ----------------
extern "C" void kernel_launch(void* const* d_in, const int* in_sizes, int n_in,
                              void* d_out, int out_size) {
    const float* x1 = (const float*)d_in[0];
    const float* x2 = (const float*)d_in[1];
    const float* cg = (const float*)d_in[2];
    const int*   r1 = (const int*)d_in[3];
    const int*   r2 = (const int*)d_in[4];
    const int*   ro = (const int*)d_in[5];

    int M = in_sizes[2];
    if (M > MAX_M) M = MAX_M;       // safety (actual M ~ 4.7K)
    int N = out_size / OUT_DIM;

    k_prep<<<NG, 1024>>>(ro, r1, r2, cg, M);

    size_t smem = (size_t)2 * OUT_DIM * PAD * sizeof(float);  // 168,960 B
    cudaFuncSetAttribute(k_main, cudaFuncAttributeMaxDynamicSharedMemorySize,
                         (int)smem);
    int nblocks = (N + ROWS - 1) / ROWS;
    k_main<<<nblocks, 640, smem>>>(x1, x2, (float*)d_out, N);
}

// round 14
// speedup vs baseline: 1.4609x; 1.4609x over previous
#include <cuda_runtime.h>
#include <cstdint>

// ---------------- configuration (fixed for this problem instance) ----------------
#define OUT_DIM   640            // rep_dim = out_dim for METADATA [64,64,32,32]
#define NG        (OUT_DIM/32)   // 20 output groups of 32
#define ROWS      32             // batch rows per main-kernel block (lane = row)
#define KCAP      24             // max terms per single output (measured <= 20)
#define MAX_M     7168           // cap on sparse term count (actual ~4.7K)
#define PAD       33             // smem row pitch (conflict-free transpose + gather)

// ---------------- device scratch (no runtime allocation allowed) ----------------
// ELL (prep output): meta_ell[o*KCAP+k] = (cg_bits<<32) | (i2<<16) | i1
__device__ unsigned long long d_ell[OUT_DIM * KCAP];
__device__ int                d_len[OUT_DIM];
// CSR (compact output): sorted by output o, rank-stable
__device__ unsigned long long d_csr[MAX_M];
__device__ int                d_start[OUT_DIM + 1];

// ---------------- prep 1: build ELL (20 blocks x 1024 threads) ----------------
// Stage ro in smem; 32 warps two-pass scan: pass1 counts per (warp-slice,
// lane-output), smem exchange -> deterministic exclusive offsets (slot = rank
// in m-order), pass2 scatters packed entries.
__global__ __launch_bounds__(1024) void k_prep(const int* __restrict__ ro,
                                               const int* __restrict__ r1,
                                               const int* __restrict__ r2,
                                               const float* __restrict__ cg,
                                               int M) {
    __shared__ int s_ro[MAX_M];
    __shared__ int s_cnt[32][32];
    int og = blockIdx.x;

    for (int i = threadIdx.x; i < M; i += 1024) s_ro[i] = ro[i];
    __syncthreads();

    int w = threadIdx.x >> 5, lane = threadIdx.x & 31;
    int o = og * 32 + lane;
    int chunk = (M + 31) >> 5;
    int mlo = w * chunk;
    int mhi = mlo + chunk; if (mhi > M) mhi = M;

    int cnt = 0;
    for (int m = mlo; m < mhi; m++) cnt += (s_ro[m] == o);
    s_cnt[w][lane] = cnt;
    __syncthreads();

    int off = 0;
    for (int ww = 0; ww < w; ww++) off += s_cnt[ww][lane];

    int k = off;
    for (int m = mlo; m < mhi; m++) {
        if (s_ro[m] == o) {
            if (k < KCAP) {
                unsigned pidx = ((unsigned)r1[m] & 0xFFFFu) |
                                (((unsigned)r2[m] & 0xFFFFu) << 16);
                d_ell[o * KCAP + k] =
                    ((unsigned long long)__float_as_uint(cg[m]) << 32) | pidx;
            }
            k++;
        }
    }

    if (w == 0) {
        int tot = 0;
        #pragma unroll
        for (int ww = 0; ww < 32; ww++) tot += s_cnt[ww][lane];
        if (tot > KCAP) tot = KCAP;
        d_len[o] = tot;
    }
}

// ---------------- prep 2: scan lens -> starts, compact ELL -> CSR (1 block) ----------------
__global__ __launch_bounds__(1024) void k_compact() {
    __shared__ int s[OUT_DIM];
    int o = threadIdx.x;
    int len = (o < OUT_DIM) ? d_len[o] : 0;
    if (o < OUT_DIM) s[o] = len;
    __syncthreads();
    for (int st = 1; st < OUT_DIM; st <<= 1) {
        int v = 0;
        if (o < OUT_DIM && o >= st) v = s[o - st];
        __syncthreads();
        if (o < OUT_DIM) s[o] += v;
        __syncthreads();
    }
    if (o < OUT_DIM) {
        int st0 = s[o] - len;
        d_start[o] = st0;
        if (o == OUT_DIM - 1) d_start[OUT_DIM] = s[o];
        for (int k = 0; k < len; k++)
            if (st0 + k < MAX_M) d_csr[st0 + k] = d_ell[o * KCAP + k];
    }
}

// ---------------- main kernel ----------------
// Block: 640 threads (20 warps), 32 batch rows; warp w owns outputs
// [32w, 32w+32), lane = batch row. x1/x2 staged TRANSPOSED (pitch 33 ->
// conflict-free STS and gathers). Term table staged as CSR in smem: per term
// one broadcast LDS.64 + two conflict-free LDS.32 + 2 FP — NO global loads in
// the inner loop (this is the fix for R13's L2-latency-bound meta reads).
// Epilogue transposes via smem for coalesced stores. No atomics.
__global__ __launch_bounds__(640) void k_main(const float* __restrict__ x1,
                                              const float* __restrict__ x2,
                                              float* __restrict__ out,
                                              int N, int Mcap) {
    extern __shared__ unsigned char smraw[];
    float* x1T = (float*)smraw;                       // [640][PAD]
    float* x2T = x1T + OUT_DIM * PAD;                 // [640][PAD]
    int*   s_start = (int*)(x2T + OUT_DIM * PAD);     // [641] (+pad to 8B)
    unsigned long long* s_meta =
        (unsigned long long*)(s_start + OUT_DIM + 8); // [Mtot]

    int tid = threadIdx.x;
    int row0 = blockIdx.x * ROWS;
    int rows_here = N - row0; if (rows_here > ROWS) rows_here = ROWS;

    // stage start table + CSR meta
    for (int i = tid; i < OUT_DIM + 1; i += 640) s_start[i] = d_start[i];
    int Mtot = d_start[OUT_DIM]; if (Mtot > Mcap) Mtot = Mcap;
    for (int i = tid; i < Mtot; i += 640) s_meta[i] = d_csr[i];

    // stage rows transposed: thread i -> (r = i/160, c4 = i%160); lanes have
    // consecutive c4 -> coalesced LDG.128; STS addrs stride 132B -> conflict-free.
    for (int i = tid; i < rows_here * (OUT_DIM / 4); i += 640) {
        int r  = i / (OUT_DIM / 4);
        int c4 = i - r * (OUT_DIM / 4);
        size_t g = ((size_t)(row0 + r) * OUT_DIM + c4 * 4) >> 2;
        float4 v1 = ((const float4*)x1)[g];
        float4 v2 = ((const float4*)x2)[g];
        int c = c4 * 4;
        x1T[(c + 0) * PAD + r] = v1.x; x1T[(c + 1) * PAD + r] = v1.y;
        x1T[(c + 2) * PAD + r] = v1.z; x1T[(c + 3) * PAD + r] = v1.w;
        x2T[(c + 0) * PAD + r] = v2.x; x2T[(c + 1) * PAD + r] = v2.y;
        x2T[(c + 2) * PAD + r] = v2.z; x2T[(c + 3) * PAD + r] = v2.w;
    }
    __syncthreads();

    int w = tid >> 5, lane = tid & 31;
    const float* b1 = x1T + lane;   // gather: b1[i1*PAD]
    const float* b2 = x2T + lane;

    float acc[32];
    #pragma unroll 1
    for (int j = 0; j < 32; j++) {
        int o = w * 32 + j;
        int ks = s_start[o], ke = s_start[o + 1];
        float a = 0.0f;
        #pragma unroll 4
        for (int k = ks; k < ke; k++) {
            unsigned long long mv = s_meta[k];      // broadcast LDS.64
            unsigned p = (unsigned)mv;
            float c = __uint_as_float((unsigned)(mv >> 32));
            int i1 = (int)(p & 0xFFFFu);
            int i2 = (int)(p >> 16);
            a = fmaf(c * b1[i1 * PAD], b2[i2 * PAD], a);
        }
        acc[j] = a;
    }

    // epilogue: transpose through smem (reuse x1T region) for coalesced stores
    __syncthreads();
    float* tile = x1T + w * (32 * PAD);   // 20 * 1056 <= 640*33 (exact fit)
    #pragma unroll
    for (int j = 0; j < 32; j++) tile[j * PAD + lane] = acc[j];
    __syncwarp();
    #pragma unroll 4
    for (int r = 0; r < 32; r++) {
        if (row0 + r < N)
            out[(size_t)(row0 + r) * OUT_DIM + w * 32 + lane] = tile[lane * PAD + r];
    }
}

// ---------------- launch ----------------
extern "C" void kernel_launch(void* const* d_in, const int* in_sizes, int n_in,
                              void* d_out, int out_size) {
    const float* x1 = (const float*)d_in[0];
    const float* x2 = (const float*)d_in[1];
    const float* cg = (const float*)d_in[2];
    const int*   r1 = (const int*)d_in[3];
    const int*   r2 = (const int*)d_in[4];
    const int*   ro = (const int*)d_in[5];

    int M = in_sizes[2];
    if (M > MAX_M) M = MAX_M;       // safety (actual M ~ 4.7K)
    int N = out_size / OUT_DIM;

    k_prep<<<NG, 1024>>>(ro, r1, r2, cg, M);
    k_compact<<<1, 1024>>>();

    // smem: rows (168,960 B) + start (2,624 B) + CSR meta (M*8 B)
    size_t smem = (size_t)2 * OUT_DIM * PAD * sizeof(float)
                + (OUT_DIM + 8) * sizeof(int)
                + (size_t)M * sizeof(unsigned long long) + 16;
    cudaFuncSetAttribute(k_main, cudaFuncAttributeMaxDynamicSharedMemorySize,
                         (int)smem);
    int nblocks = (N + ROWS - 1) / ROWS;
    k_main<<<nblocks, 640, smem>>>(x1, x2, (float*)d_out, N, M);
}